// round 9
// baseline (speedup 1.0000x reference)
#include <cuda_runtime.h>
#include <math.h>

#define T_SNAP 4
#define EQ     4096
#define NNODES 8192
#define H      32
#define BCAP   32                // in-edge bucket capacity per (t, node)
#define RCAP   128               // per-query reach-set capacity
#define HSZ    128               // per-thread hash-set slots (power of 2)
#define NQ     (T_SNAP * EQ)     // 16384 queries
#define NB     (EQ * 3)          // pooled nodes (GRU batch)

#define GRID1  296               // 2 blocks/SM, all-resident (barrier-safe)
#define BLK1   256

#define GRID2  48                // NB / BLK2, no barrier
#define BLK2   256
#define MAXU   BLK2              // worst-case uniques per block

// Scratch (static device globals, zero-initialized; every call restores zeros)
__device__ int    g_bcnt[T_SNAP * NNODES];
__device__ int    g_bsrc[T_SNAP * NNODES * BCAP];
__device__ float  g_tops[NQ * 3];
__device__ int    g_cnt1;                  // barrier arrive counter (self-reset)
__device__ volatile int g_flag1;           // barrier release flag (reset by k2)

__device__ __forceinline__ float fast_sigmoid(float x) {
    return 1.f / (1.f + __expf(-x));
}
__device__ __forceinline__ float fast_tanh(float x) {
    return 2.f / (1.f + __expf(-2.f * x)) - 1.f;
}

// per-thread (local memory) open-addressing hash set; 0 = empty, key = x+1
__device__ __forceinline__ bool hs_add(int* hs, int x) {
    unsigned h = ((unsigned)x * 2654435761u) >> 25;   // 7 bits
    for (;;) {
        int c = hs[h];
        if (c == x + 1) return false;
        if (c == 0) { hs[h] = x + 1; return true; }
        h = (h + 1) & (HSZ - 1);
    }
}
__device__ __forceinline__ bool hs_has(const int* hs, int x) {
    unsigned h = ((unsigned)x * 2654435761u) >> 25;
    for (;;) {
        int c = hs[h];
        if (c == x + 1) return true;
        if (c == 0) return false;
        h = (h + 1) & (HSZ - 1);
    }
}

// 2-hop backward BFS from seed; list (iteration) + hash set (membership)
__device__ __forceinline__ int bfs2(int t, int seed, int* R, int* HS) {
    R[0] = seed;
    hs_add(HS, seed);
    int n = 1, s = 0, e = 1;
#pragma unroll
    for (int hop = 0; hop < 2; hop++) {
        for (int i = s; i < e; i++) {
            int node = R[i];
            int c = g_bcnt[t * NNODES + node];
            if (c > BCAP) c = BCAP;
            const int* b = &g_bsrc[(t * NNODES + node) * BCAP];
            for (int j = 0; j < c; j++) {
                int src = b[j];
                if (n < RCAP && hs_add(HS, src)) R[n++] = src;
            }
        }
        s = e; e = n;
    }
    return n;
}

// ---------------------------------------------------------------------------
// k1: scatter edges -> grid barrier -> thread-per-(t,q) query + top-3
__global__ void __launch_bounds__(BLK1, 2)
k_graph(const int* __restrict__ ei) {
    int idx = blockIdx.x * BLK1 + threadIdx.x;

    // ---- phase A: scatter (t, e) -> bucket of srcs at dst ----
    if (idx < NQ) {
        int t = idx >> 12;             // EQ = 4096
        int e = idx & (EQ - 1);
        int src = __ldg(&ei[t * 2 * EQ + e]);
        int dst = __ldg(&ei[t * 2 * EQ + EQ + e]);
        int pos = atomicAdd(&g_bcnt[t * NNODES + dst], 1);
        if (pos < BCAP) g_bsrc[(t * NNODES + dst) * BCAP + pos] = src;
    }

    // ---- grid barrier (flag-based; flag reset by k2) ----
    __syncthreads();
    if (threadIdx.x == 0) {
        __threadfence();
        if (atomicAdd(&g_cnt1, 1) == GRID1 - 1) {
            g_cnt1 = 0;
            __threadfence();
            g_flag1 = 1;
        } else {
            while (g_flag1 == 0) {}
        }
        __threadfence();
    }
    __syncthreads();

    // ---- phase B: thread-per-query ----
    if ((idx & 3) != 0) return;
    int qi = idx >> 2;
    if (qi >= NQ) return;
    int t = qi >> 12;
    int q = qi & (EQ - 1);
    int u = __ldg(&ei[(T_SNAP - 1) * 2 * EQ + q]);
    int v = __ldg(&ei[(T_SNAP - 1) * 2 * EQ + EQ + q]);

    int Ru[RCAP], Rv[RCAP];
    int HSu[HSZ], HSv[HSZ];
#pragma unroll 8
    for (int i = 0; i < HSZ; i++) { HSu[i] = 0; HSv[i] = 0; }

    int nu = bfs2(t, u, Ru, HSu);
    int nv = bfs2(t, v, Rv, HSv);

    float t0 = 0.f, t1 = 0.f, t2 = 0.f;
    for (int pass = 0; pass < 2; pass++) {
        const int* L = pass ? Rv : Ru;
        int nL = pass ? nv : nu;
        for (int i = 0; i < nL; i++) {
            int node = L[i];
            bool inRu, inRv;
            if (pass == 0) {
                inRu = true;
                inRv = hs_has(HSv, node);
            } else {
                if (hs_has(HSu, node)) continue;   // handled in pass 0
                inRu = false;
                inRv = true;
            }
            int c = g_bcnt[t * NNODES + node];
            if (c > BCAP) c = BCAP;
            const int* b = &g_bsrc[(t * NNODES + node) * BCAP];
            int d = 0;
            for (int j = 0; j < c; j++) {
                int src = b[j];
                bool su = inRu && hs_has(HSu, src);
                bool sv = inRv && hs_has(HSv, src);
                if (su || sv) d++;
            }
            float f = (float)d;
            if (f > t0)      { t2 = t1; t1 = t0; t0 = f; }
            else if (f > t1) { t2 = t1; t1 = f; }
            else if (f > t2) { t2 = f; }
        }
    }
    g_tops[qi * 3 + 0] = t0;
    g_tops[qi * 3 + 1] = t1;
    g_tops[qi * 3 + 2] = t2;
}

// ---------------------------------------------------------------------------
// k2: block-local dedup -> warp-per-unique GRU -> ballot scatter. No barriers.
__global__ void __launch_bounds__(BLK2)
k_rnn(const float* __restrict__ Wg,  const float* __restrict__ bg,
      const float* __restrict__ Wih, const float* __restrict__ Whh,
      const float* __restrict__ bih, const float* __restrict__ bhh,
      float* __restrict__ out) {
    __shared__ float sWih[3 * H * H];      // [j*H + kk]
    __shared__ float sWhhT[H][3 * H];      // [kk][j], conflict-free
    __shared__ float sgi[33][3 * H];       // gi(v), degrees 0..32 (<= BCAP)
    __shared__ float sbhh[3 * H];
    __shared__ float sWg[H], sbg[H];
    __shared__ int   skey[512], svid[512];
    __shared__ int   srep[MAXU];           // representative pooled node per unique
    __shared__ int   suid[BLK2];           // unique id per local node
    __shared__ int   sucnt;

    int tid = threadIdx.x;
    int idx = blockIdx.x * BLK2 + tid;

    if (idx == 0) g_flag1 = 0;             // reset k1 barrier flag for next call
    // clear bucket counters for next call (queries already consumed them)
    for (int i = idx; i < T_SNAP * NNODES; i += GRID2 * BLK2) g_bcnt[i] = 0;

    for (int i = tid; i < 3 * H * H; i += BLK2) {
        sWih[i] = Wih[i];
        int j = i / H, kk = i - j * H;
        sWhhT[kk][j] = Whh[i];
    }
    if (tid < 3 * H) sbhh[tid] = bhh[tid];
    if (tid < H) { sWg[tid] = Wg[tid]; sbg[tid] = bg[tid]; }
    for (int i = tid; i < 512; i += BLK2) { skey[i] = 0; svid[i] = -1; }
    if (tid == 0) sucnt = 0;
    __syncthreads();

    // gi(v) table in SMEM: gi[v][j] = bih[j] + sum_k Wih[j,k]*relu(v*Wg[k]+bg[k])
    for (int i = tid; i < 33 * 3 * H; i += BLK2) {
        int v = i / (3 * H);
        int j = i - v * (3 * H);
        float acc = __ldg(&bih[j]);
        float fv = (float)v;
#pragma unroll
        for (int kk = 0; kk < H; kk++) {
            float xk = fmaxf(fv * sWg[kk] + sbg[kk], 0.f);
            acc += sWih[j * H + kk] * xk;
        }
        sgi[v][j] = acc;
    }

    // ---- block-local dedup of degree 4-tuples (degrees <= 32, always pack) --
    {
        int b = idx;                       // GRID2*BLK2 == NB exactly
        int q = b / 3, p = b - q * 3;
        int i0 = (int)g_tops[(0 * EQ + q) * 3 + p];
        int i1 = (int)g_tops[(1 * EQ + q) * 3 + p];
        int i2 = (int)g_tops[(2 * EQ + q) * 3 + p];
        int i3 = (int)g_tops[(3 * EQ + q) * 3 + p];
        int key = i0 | (i1 << 8) | (i2 << 16) | (i3 << 24) | 0x40000000;
        unsigned h = ((unsigned)key * 2654435761u >> 14) & 511u;
        int myslot;
        for (;;) {
            int old = atomicCAS(&skey[h], 0, key);
            if (old == 0) {
                int u = atomicAdd(&sucnt, 1);
                svid[h] = u;
                srep[u] = b;
                myslot = (int)h;
                break;
            }
            if (old == key) { myslot = (int)h; break; }
            h = (h + 1) & 511u;
        }
        __syncthreads();
        suid[tid] = svid[myslot];
    }
    __syncthreads();

    // ---- warp-per-unique GRU + ballot scatter to owning pooled nodes ----
    int ucnt = sucnt;
    int lane = tid & 31;
    int wp   = tid >> 5;
    for (int u = wp; u < ucnt; u += BLK2 / 32) {
        int rb = srep[u];
        int rq = rb / 3, rp = rb - rq * 3;

        float pr[4], pz[4], pg[4];
#pragma unroll
        for (int t = 0; t < T_SNAP; t++) {
            int iv = (int)g_tops[((t << 12) + rq) * 3 + rp];
            const float* gp = sgi[iv];
            pr[t] = gp[lane];
            pz[t] = gp[H + lane];
            pg[t] = gp[2 * H + lane];
        }

        float h = 0.f;
#pragma unroll
        for (int t = 0; t < T_SNAP; t++) {
            float hr = sbhh[lane], hz = sbhh[H + lane], hg = sbhh[2 * H + lane];
#pragma unroll
            for (int kk = 0; kk < H; kk++) {
                float hk = __shfl_sync(0xffffffffu, h, kk);
                hr += sWhhT[kk][lane]         * hk;
                hz += sWhhT[kk][H + lane]     * hk;
                hg += sWhhT[kk][2 * H + lane] * hk;
            }
            float r = fast_sigmoid(pr[t] + hr);
            float z = fast_sigmoid(pz[t] + hz);
            float n = fast_tanh(pg[t] + r * hg);
            h = (1.f - z) * n + z * h;
        }

        // write h to every pooled node in this block with uid == u
        for (int base = 0; base < BLK2; base += 32) {
            unsigned m = __ballot_sync(0xffffffffu, suid[base + lane] == u);
            while (m) {
                int bb = __ffs(m) - 1;
                m &= m - 1;
                out[(blockIdx.x * BLK2 + base + bb) * H + lane] = h;
            }
        }
    }
}

// ---------------------------------------------------------------------------
extern "C" void kernel_launch(void* const* d_in, const int* in_sizes, int n_in,
                              void* d_out, int out_size) {
    const int*   ei  = (const int*)d_in[0];
    const float* Wg  = (const float*)d_in[1];
    const float* bg  = (const float*)d_in[2];
    const float* Wih = (const float*)d_in[3];
    const float* Whh = (const float*)d_in[4];
    const float* bih = (const float*)d_in[5];
    const float* bhh = (const float*)d_in[6];
    float* out = (float*)d_out;

    k_graph<<<GRID1, BLK1>>>(ei);
    k_rnn  <<<GRID2, BLK2>>>(Wg, bg, Wih, Whh, bih, bhh, out);
}

// round 10
// speedup vs baseline: 1.1135x; 1.1135x over previous
#include <cuda_runtime.h>
#include <math.h>

#define T_SNAP 4
#define EQ     4096
#define NNODES 8192
#define H      32
#define BCAP   32                // in-edge bucket capacity per (t, node)
#define RCAP   128               // per-query reach-set capacity
#define HT     16384             // global hash table slots (power of 2)
#define NQ     (T_SNAP * EQ)     // 16384 queries
#define NB     (EQ * 3)          // pooled nodes (GRU batch)

#define GRID1  296               // 2 blocks/SM, all-resident (barrier-safe)
#define BLK1   256

#define GRID2B 96                // GRU: 96 x 128 = 384 warps (uniques <= 384)
#define BLK2B  128

// Scratch (static device globals, zero-initialized; every call restores zeros)
__device__ int    g_bcnt[T_SNAP * NNODES];
__device__ int    g_bsrc[T_SNAP * NNODES * BCAP];
__device__ float  g_tops[NQ * 3];
__device__ int    g_htkey[HT];             // 0 = empty
__device__ float4 g_slotv[HT];
__device__ float  g_uh[HT * H];
__device__ int    g_bslot[NB];
__device__ int    g_uniq[NB];
__device__ int    g_uniq_cnt;
__device__ int    g_cnt1;                  // barrier arrive counter (self-reset)
__device__ volatile int g_flag1;           // barrier release flag (reset by k2a)

__device__ __forceinline__ float fast_sigmoid(float x) {
    return 1.f / (1.f + __expf(-x));
}
__device__ __forceinline__ float fast_tanh(float x) {
    return 2.f / (1.f + __expf(-2.f * x)) - 1.f;
}

__device__ __forceinline__ bool in_list(const int* l, int n, int x) {
    for (int i = 0; i < n; i++)
        if (l[i] == x) return true;
    return false;
}

// 2-hop backward BFS from seed within snapshot t; returns set size
__device__ __forceinline__ int bfs2(int t, int seed, int* R) {
    R[0] = seed;
    int n = 1, s = 0, e = 1;
#pragma unroll
    for (int hop = 0; hop < 2; hop++) {
        for (int i = s; i < e; i++) {
            int node = R[i];
            int c = g_bcnt[t * NNODES + node];
            if (c > BCAP) c = BCAP;
            const int* b = &g_bsrc[(t * NNODES + node) * BCAP];
            for (int j = 0; j < c; j++) {
                int src = b[j];
                if (!in_list(R, n, src) && n < RCAP) R[n++] = src;
            }
        }
        s = e; e = n;
    }
    return n;
}

// ---------------------------------------------------------------------------
// k1: scatter edges -> grid barrier -> thread-per-(t,q) query + top-3
// (round-8 version verbatim: measured ~24 us)
__global__ void __launch_bounds__(BLK1, 2)
k_graph(const int* __restrict__ ei) {
    int idx = blockIdx.x * BLK1 + threadIdx.x;

    // ---- phase A: scatter (t, e) -> bucket of srcs at dst ----
    if (idx < NQ) {
        int t = idx >> 12;             // EQ = 4096
        int e = idx & (EQ - 1);
        int src = __ldg(&ei[t * 2 * EQ + e]);
        int dst = __ldg(&ei[t * 2 * EQ + EQ + e]);
        int pos = atomicAdd(&g_bcnt[t * NNODES + dst], 1);
        if (pos < BCAP) g_bsrc[(t * NNODES + dst) * BCAP + pos] = src;
    }

    // ---- grid barrier (flag-based; flag reset by k2a) ----
    __syncthreads();
    if (threadIdx.x == 0) {
        __threadfence();
        if (atomicAdd(&g_cnt1, 1) == GRID1 - 1) {
            g_cnt1 = 0;
            __threadfence();
            g_flag1 = 1;
        } else {
            while (g_flag1 == 0) {}
        }
        __threadfence();
    }
    __syncthreads();

    // ---- phase B: thread-per-query, every 4th lane for MLP headroom ----
    if ((idx & 3) != 0) return;
    int qi = idx >> 2;
    if (qi >= NQ) return;
    int t = qi >> 12;
    int q = qi & (EQ - 1);
    int u = __ldg(&ei[(T_SNAP - 1) * 2 * EQ + q]);
    int v = __ldg(&ei[(T_SNAP - 1) * 2 * EQ + EQ + q]);

    int Ru[RCAP], Rv[RCAP];
    int nu = bfs2(t, u, Ru);
    int nv = bfs2(t, v, Rv);

    float t0 = 0.f, t1 = 0.f, t2 = 0.f;
    for (int pass = 0; pass < 2; pass++) {
        const int* L = pass ? Rv : Ru;
        int nL = pass ? nv : nu;
        for (int i = 0; i < nL; i++) {
            int node = L[i];
            bool inRu, inRv;
            if (pass == 0) {
                inRu = true;
                inRv = in_list(Rv, nv, node);
            } else {
                inRu = in_list(Ru, nu, node);
                if (inRu) continue;        // handled in pass 0
                inRv = true;
            }
            int c = g_bcnt[t * NNODES + node];
            if (c > BCAP) c = BCAP;
            const int* b = &g_bsrc[(t * NNODES + node) * BCAP];
            int d = 0;
            for (int j = 0; j < c; j++) {
                int src = b[j];
                bool su = inRu && in_list(Ru, nu, src);
                bool sv = inRv && in_list(Rv, nv, src);
                if (su || sv) d++;
            }
            float f = (float)d;
            if (f > t0)      { t2 = t1; t1 = t0; t0 = f; }
            else if (f > t1) { t2 = t1; t1 = f; }
            else if (f > t2) { t2 = f; }
        }
    }
    g_tops[qi * 3 + 0] = t0;
    g_tops[qi * 3 + 1] = t1;
    g_tops[qi * 3 + 2] = t2;
}

// ---------------------------------------------------------------------------
// k2a: global dedup of degree 4-tuples (load-before-CAS) + bcnt clear
__global__ void __launch_bounds__(256)
k_dedup() {
    int idx = blockIdx.x * 256 + threadIdx.x;
    if (idx == 0) g_flag1 = 0;          // reset k1 barrier flag for next call

    // clear bucket counters for next call (queries already consumed them)
    for (int i = idx; i < T_SNAP * NNODES; i += NB) g_bcnt[i] = 0;

    if (idx >= NB) return;
    int b = idx;
    int q = b / 3, p = b - q * 3;
    float v0 = g_tops[(0 * EQ + q) * 3 + p];
    float v1 = g_tops[(1 * EQ + q) * 3 + p];
    float v2 = g_tops[(2 * EQ + q) * 3 + p];
    float v3 = g_tops[(3 * EQ + q) * 3 + p];
    // degrees are <= BCAP = 32: always packable, never zero with the tag bit
    int key = (int)v0 | ((int)v1 << 8) | ((int)v2 << 16) | ((int)v3 << 24)
            | 0x40000000;
    unsigned hsl = ((unsigned)key * 2654435761u) & (HT - 1);
    int slot;
    for (;;) {
        int cur = ((volatile int*)g_htkey)[hsl];       // fast path: no atomic
        if (cur == key) { slot = (int)hsl; break; }
        if (cur == 0) {
            int old = atomicCAS(&g_htkey[hsl], 0, key);
            if (old == 0) {
                g_slotv[hsl] = make_float4(v0, v1, v2, v3);
                int u = atomicAdd(&g_uniq_cnt, 1);
                g_uniq[u] = (int)hsl;
                slot = (int)hsl;
                break;
            }
            if (old == key) { slot = (int)hsl; break; }
        }
        hsl = (hsl + 1) & (HT - 1);
    }
    g_bslot[b] = slot;
}

// ---------------------------------------------------------------------------
// k2b: warp-per-unique GRU; gi(v) table (v<=32) built in SMEM per block
__global__ void __launch_bounds__(BLK2B)
k_gru(const float* __restrict__ Wg,  const float* __restrict__ bg,
      const float* __restrict__ Wih, const float* __restrict__ Whh,
      const float* __restrict__ bih, const float* __restrict__ bhh) {
    __shared__ float sWih[3 * H * H];      // [j*H + kk] (for gi build)
    __shared__ float sWhhT[H][3 * H];      // [kk][j], conflict-free
    __shared__ float sgi[33][3 * H];       // gi(v), degrees 0..32
    __shared__ float sbhh[3 * H];
    __shared__ float sWg[H], sbg[H];

    int tid = threadIdx.x;
    for (int i = tid; i < 3 * H * H; i += BLK2B) {
        sWih[i] = Wih[i];
        int j = i / H, kk = i - j * H;
        sWhhT[kk][j] = Whh[i];
    }
    if (tid < 3 * H) sbhh[tid] = bhh[tid];
    if (tid < H) { sWg[tid] = Wg[tid]; sbg[tid] = bg[tid]; }
    __syncthreads();

    // gi[v][j] = bih[j] + sum_k Wih[j,k] * relu(v*Wg[k] + bg[k])
    for (int i = tid; i < 33 * 3 * H; i += BLK2B) {
        int v = i / (3 * H);
        int j = i - v * (3 * H);
        float acc = __ldg(&bih[j]);
        float fv = (float)v;
#pragma unroll
        for (int kk = 0; kk < H; kk++) {
            float xk = fmaxf(fv * sWg[kk] + sbg[kk], 0.f);
            acc += sWih[j * H + kk] * xk;
        }
        sgi[v][j] = acc;
    }
    __syncthreads();

    int cnt = g_uniq_cnt;
    int lane = tid & 31;
    int w = blockIdx.x * (BLK2B / 32) + (tid >> 5);
    for (int u = w; u < cnt; u += GRID2B * (BLK2B / 32)) {
        int slot = g_uniq[u];
        float4 vv = g_slotv[slot];
        float vs[4] = {vv.x, vv.y, vv.z, vv.w};

        float pr[4], pz[4], pg[4];
#pragma unroll
        for (int t = 0; t < T_SNAP; t++) {
            const float* gp = sgi[(int)vs[t]];         // degree <= 32 always
            pr[t] = gp[lane];
            pz[t] = gp[H + lane];
            pg[t] = gp[2 * H + lane];
        }

        float h = 0.f;
#pragma unroll
        for (int t = 0; t < T_SNAP; t++) {
            float hr = sbhh[lane], hz = sbhh[H + lane], hg = sbhh[2 * H + lane];
#pragma unroll
            for (int kk = 0; kk < H; kk++) {
                float hk = __shfl_sync(0xffffffffu, h, kk);
                hr += sWhhT[kk][lane]         * hk;
                hz += sWhhT[kk][H + lane]     * hk;
                hg += sWhhT[kk][2 * H + lane] * hk;
            }
            float r = fast_sigmoid(pr[t] + hr);
            float z = fast_sigmoid(pz[t] + hz);
            float n = fast_tanh(pg[t] + r * hg);
            h = (1.f - z) * n + z * h;
        }
        g_uh[slot * H + lane] = h;
        if (lane == 0) g_htkey[slot] = 0;   // reset consumed slot for next call
    }
}

// ---------------------------------------------------------------------------
// k2c: parallel coalesced gather to output + uniq counter reset
__global__ void __launch_bounds__(256)
k_gather(float* __restrict__ out) {
    int i = blockIdx.x * 256 + threadIdx.x;
    if (i == 0) g_uniq_cnt = 0;            // reset for next call
    if (i >= NB * H) return;
    int b = i >> 5;
    int j = i & (H - 1);
    out[i] = g_uh[g_bslot[b] * H + j];
}

// ---------------------------------------------------------------------------
extern "C" void kernel_launch(void* const* d_in, const int* in_sizes, int n_in,
                              void* d_out, int out_size) {
    const int*   ei  = (const int*)d_in[0];
    const float* Wg  = (const float*)d_in[1];
    const float* bg  = (const float*)d_in[2];
    const float* Wih = (const float*)d_in[3];
    const float* Whh = (const float*)d_in[4];
    const float* bih = (const float*)d_in[5];
    const float* bhh = (const float*)d_in[6];
    float* out = (float*)d_out;

    k_graph <<<GRID1, BLK1>>>(ei);
    k_dedup <<<NB / 256, 256>>>();
    k_gru   <<<GRID2B, BLK2B>>>(Wg, bg, Wih, Whh, bih, bhh);
    k_gather<<<(NB * H + 255) / 256, 256>>>(out);
}